// round 12
// baseline (speedup 1.0000x reference)
#include <cuda_runtime.h>
#include <cuda_bf16.h>
#include <math.h>
#include <stdint.h>

#define NMAX 100000
#define EMAX 1600000
#define DIM 64

// node features stored as bf16 (32 uints = 64 bf16 per row)
__device__ unsigned int g_hW[(size_t)NMAX * 32];
__device__ float g_acc[(size_t)NMAX * DIM];
__device__ float g_pool[64 * DIM];
__device__ int   g_is64;
__device__ int   g_deg[NMAX];
__device__ int   g_off[NMAX + 1];
__device__ int   g_cursor[NMAX];
__device__ int   g_bsum[1024];
__device__ int   g_srcs[EMAX];

// pre-split weight planes (hi/lo tf32): W0a | W0b | Wsb0 | Wsb1 | Wsa0 | Wsa1
#define OFF_W0A  0
#define OFF_W0B  8192
#define OFF_WSB0 12288
#define OFF_WSB1 16384
#define OFF_WSA0 20480
#define OFF_WSA1 24576
#define W_TOTAL  28672
__device__ float g_whi[W_TOTAL];
__device__ float g_wlo[W_TOTAL];

// ---------------------------------------------------------------------------
__device__ __forceinline__ float tf32r(float x) {
    uint32_t u;
    asm("cvt.rna.tf32.f32 %0, %1;" : "=r"(u) : "f"(x));
    return __uint_as_float(u);
}

__device__ __forceinline__ void split_tf32(float x, float& hi, float& lo) {
    float h = tf32r(x);
    hi = h;
    lo = tf32r(x - h);
}

__device__ __forceinline__ void mma_tf32(float* c, uint32_t a0, uint32_t a1,
                                         uint32_t a2, uint32_t a3,
                                         uint32_t b0, uint32_t b1) {
    asm volatile(
        "mma.sync.aligned.m16n8k8.row.col.f32.tf32.tf32.f32 "
        "{%0,%1,%2,%3}, {%4,%5,%6,%7}, {%8,%9}, {%0,%1,%2,%3};"
        : "+f"(c[0]), "+f"(c[1]), "+f"(c[2]), "+f"(c[3])
        : "r"(a0), "r"(a1), "r"(a2), "r"(a3), "r"(b0), "r"(b1));
}

__device__ __forceinline__ unsigned int pack_bf(float a, float b) {
    __nv_bfloat162 p = __floats2bfloat162_rn(a, b);
    return *(unsigned int*)&p;
}

__device__ __forceinline__ float4 unpack_bf4(uint2 u) {
    float2 f0 = __bfloat1622float2(*(__nv_bfloat162*)&u.x);
    float2 f1 = __bfloat1622float2(*(__nv_bfloat162*)&u.y);
    return make_float4(f0.x, f0.y, f1.x, f1.y);
}

// store weight float4 (cols n..n+3 of row k) into fragment-major smem layout:
// offset(k,n) = ((k*2+half)*8 + gid)*4 + nf  with n = half*32 + nf*8 + gid.
__device__ __forceinline__ void stage_frag(float* P, int k, int n, float4 v) {
    int half = n >> 5;
    int nf   = (n >> 3) & 3;
    int gid0 = n & 7;
    int base = (k * 2 + half) * 32 + nf;
    P[base + (gid0 + 0) * 4] = v.x;
    P[base + (gid0 + 1) * 4] = v.y;
    P[base + (gid0 + 2) * 4] = v.z;
    P[base + (gid0 + 3) * 4] = v.w;
}

// ---------------------------------------------------------------------------
// zero + dtype detect + weight split (fused setup kernel)
__global__ void zero_split_kernel(const int* __restrict__ e, int M,
    const float* __restrict__ W0a, const float* __restrict__ W0b,
    const float* __restrict__ Wsa, const float* __restrict__ Wsb)
{
    int t = blockIdx.x * blockDim.x + threadIdx.x;   // 64*256 = 16384 threads
    if (t == 0) {
        int all0 = 1;
        #pragma unroll
        for (int i = 1; i < 64; i += 2) all0 &= (e[i] == 0);
        g_is64 = all0;
    }
    if (t < 64 * DIM) g_pool[t] = 0.0f;
    for (int i = t; i < M; i += 16384) g_deg[i] = 0;
    for (int i = t; i < W_TOTAL; i += 16384) {
        float v;
        if      (i < OFF_W0B)  v = W0a[i];
        else if (i < OFF_WSB0) v = W0b[i - OFF_W0B];
        else if (i < OFF_WSB1) v = Wsb[i - OFF_WSB0];
        else if (i < OFF_WSA0) v = Wsb[4096 + i - OFF_WSB1];
        else if (i < OFF_WSA1) v = Wsa[i - OFF_WSA0];
        else                   v = Wsa[4096 + i - OFF_WSA1];
        float hi, lo; split_tf32(v, hi, lo);
        g_whi[i] = hi; g_wlo[i] = lo;
    }
}

// ---------------------------------------------------------------------------
// CSR build
__global__ __launch_bounds__(256) void hist_kernel(const void* __restrict__ eidx, int E) {
    int e = blockIdx.x * 256 + threadIdx.x;
    if (e >= E) return;
    int dst;
    if (g_is64) dst = (int)__ldg(&((const long long*)eidx)[E + e]);
    else        dst = __ldg(&((const int*)eidx)[E + e]);
    atomicAdd(&g_deg[dst], 1);
}

__global__ __launch_bounds__(256) void scan_local_kernel(int M) {
    __shared__ int warp_tot[8];
    __shared__ int wbase[8];
    const int t = threadIdx.x;
    const int idx0 = blockIdx.x * 1024 + t * 4;
    int v[4];
    #pragma unroll
    for (int i = 0; i < 4; i++) v[i] = (idx0 + i < M) ? g_deg[idx0 + i] : 0;
    int tot = v[0] + v[1] + v[2] + v[3];
    const int lane = t & 31, w = t >> 5;
    int sc = tot;
    #pragma unroll
    for (int o = 1; o < 32; o <<= 1) {
        int n = __shfl_up_sync(0xffffffffu, sc, o);
        if (lane >= o) sc += n;
    }
    if (lane == 31) warp_tot[w] = sc;
    __syncthreads();
    if (t == 0) {
        int s = 0;
        #pragma unroll
        for (int i = 0; i < 8; i++) { wbase[i] = s; s += warp_tot[i]; }
        g_bsum[blockIdx.x] = s;
    }
    __syncthreads();
    int run = sc - tot + wbase[w];
    #pragma unroll
    for (int i = 0; i < 4; i++) {
        if (idx0 + i < M) g_off[idx0 + i] = run;
        run += v[i];
    }
}

__global__ __launch_bounds__(256) void scan_add_kernel(int M, int E) {
    __shared__ int red[256];
    const int t = threadIdx.x;
    const int nb = blockIdx.x >> 2;        // 256-chunks never cross 1024-chunks
    int s = 0;
    for (int i = t; i < nb; i += 256) s += g_bsum[i];
    red[t] = s;
    __syncthreads();
    #pragma unroll
    for (int o = 128; o > 0; o >>= 1) {
        if (t < o) red[t] += red[t + o];
        __syncthreads();
    }
    const int base = red[0];
    int i = blockIdx.x * 256 + t;
    if (i < M) {
        int o = g_off[i] + base;
        g_off[i] = o;
        g_cursor[i] = o;
    } else if (i == M) {
        g_off[M] = E;
    }
}

__global__ __launch_bounds__(256) void reorder_kernel(const void* __restrict__ eidx, int E) {
    int e = blockIdx.x * 256 + threadIdx.x;
    if (e >= E) return;
    int src, dst;
    if (g_is64) {
        const long long* p = (const long long*)eidx;
        src = (int)__ldg(&p[e]); dst = (int)__ldg(&p[E + e]);
    } else {
        const int* p = (const int*)eidx;
        src = __ldg(&p[e]); dst = __ldg(&p[E + e]);
    }
    int pos = atomicAdd(&g_cursor[dst], 1);
    g_srcs[pos] = src;
}

// ---------------------------------------------------------------------------
// Gather: one warp per dst node; half-warp h, lane j owns uint2 j (4 bf16).
__global__ __launch_bounds__(256) void gather_kernel(int M) {
    const int warp = (blockIdx.x * 256 + threadIdx.x) >> 5;
    if (warp >= M) return;
    const int lane = threadIdx.x & 31;
    const int h = lane >> 4;
    const int j = lane & 15;

    const uint2* hw = (const uint2*)g_hW;
    const int beg = g_off[warp], end = g_off[warp + 1];
    float4 acc = make_float4(0.f, 0.f, 0.f, 0.f);
    int k = beg + h;
    for (; k + 6 < end; k += 8) {
        int s0 = __ldg(&g_srcs[k]);
        int s1 = __ldg(&g_srcs[k + 2]);
        int s2 = __ldg(&g_srcs[k + 4]);
        int s3 = __ldg(&g_srcs[k + 6]);
        float4 v0 = unpack_bf4(__ldg(hw + (size_t)s0 * 16 + j));
        float4 v1 = unpack_bf4(__ldg(hw + (size_t)s1 * 16 + j));
        float4 v2 = unpack_bf4(__ldg(hw + (size_t)s2 * 16 + j));
        float4 v3 = unpack_bf4(__ldg(hw + (size_t)s3 * 16 + j));
        acc.x += (v0.x + v1.x) + (v2.x + v3.x);
        acc.y += (v0.y + v1.y) + (v2.y + v3.y);
        acc.z += (v0.z + v1.z) + (v2.z + v3.z);
        acc.w += (v0.w + v1.w) + (v2.w + v3.w);
    }
    for (; k < end; k += 2) {
        int s0 = __ldg(&g_srcs[k]);
        float4 v0 = unpack_bf4(__ldg(hw + (size_t)s0 * 16 + j));
        acc.x += v0.x; acc.y += v0.y; acc.z += v0.z; acc.w += v0.w;
    }
    acc.x += __shfl_down_sync(0xffffffffu, acc.x, 16);
    acc.y += __shfl_down_sync(0xffffffffu, acc.y, 16);
    acc.z += __shfl_down_sync(0xffffffffu, acc.z, 16);
    acc.w += __shfl_down_sync(0xffffffffu, acc.w, 16);
    if (h == 0) {
        float4 self = unpack_bf4(__ldg(hw + (size_t)warp * 16 + j));
        acc.x += self.x; acc.y += self.y; acc.z += self.z; acc.w += self.w;
        *((float4*)(g_acc + (size_t)warp * DIM) + j) = acc;
    }
}

// ---------------------------------------------------------------------------
// Layer-0 first linear: hW = X[M,128] @ W0a[128,64] -> bf16.
// 128 rows/block; A single-tf32, B = hi+lo fragment-major planes (LDS.128).
__global__ __launch_bounds__(256) void lin0_kernel(const float* __restrict__ X, int M)
{
    extern __shared__ float sm[];
    float* Xs = sm;                 // 128 x 132
    float* Wh = Xs + 128 * 132;     // 4096 (fragment-major)
    float* Wl = Wh + 4096;          // 4096
    const int t = threadIdx.x;
    const int row0 = blockIdx.x * 128;

    for (int i = t; i < 128 * 32; i += 256) {
        int r = i >> 5, kk = i & 31;
        int gr = row0 + r; if (gr >= M) gr = M - 1;
        float4 v = *(const float4*)(X + (size_t)gr * 128 + kk * 4);
        v.x = tf32r(v.x); v.y = tf32r(v.y); v.z = tf32r(v.z); v.w = tf32r(v.w);
        *(float4*)(Xs + r * 132 + kk * 4) = v;
    }

    const int w = t >> 5, lane = t & 31;
    const int gid = lane >> 2, tig = lane & 3;
    const int rows0 = w * 16;           // warp-exclusive rows

    float c[2][4][4] = {};
    #pragma unroll
    for (int ks = 0; ks < 2; ks++) {
        __syncthreads();
        for (int i = t; i < 64 * 16; i += 256) {
            int k = i >> 4, q = i & 15;
            float4 h4 = *(const float4*)(g_whi + OFF_W0A + (ks * 64 + k) * 64 + q * 4);
            float4 l4 = *(const float4*)(g_wlo + OFF_W0A + (ks * 64 + k) * 64 + q * 4);
            stage_frag(Wh, k, q * 4, h4);
            stage_frag(Wl, k, q * 4, l4);
        }
        __syncthreads();
        #pragma unroll
        for (int k0 = 0; k0 < 8; k0++) {
            const int kx = ks * 64 + k0 * 8;
            const int kw = k0 * 8;
            int i0 = (rows0 + gid) * 132 + kx + tig;
            int i1 = (rows0 + gid + 8) * 132 + kx + tig;
            uint32_t a0 = __float_as_uint(Xs[i0]);
            uint32_t a1 = __float_as_uint(Xs[i1]);
            uint32_t a2 = __float_as_uint(Xs[i0 + 4]);
            uint32_t a3 = __float_as_uint(Xs[i1 + 4]);
            #pragma unroll
            for (int half = 0; half < 2; half++) {
                int bb = ((kw + tig) * 2 + half) * 32 + gid * 4;
                float4 bh0 = *(float4*)(Wh + bb);
                float4 bh1 = *(float4*)(Wh + bb + 256);
                float4 bl0 = *(float4*)(Wl + bb);
                float4 bl1 = *(float4*)(Wl + bb + 256);
                const float* ph0 = (const float*)&bh0;
                const float* ph1 = (const float*)&bh1;
                const float* pl0 = (const float*)&bl0;
                const float* pl1 = (const float*)&bl1;
                #pragma unroll
                for (int nf = 0; nf < 4; nf++) {
                    mma_tf32(c[half][nf], a0, a1, a2, a3,
                             __float_as_uint(ph0[nf]), __float_as_uint(ph1[nf]));
                    mma_tf32(c[half][nf], a0, a1, a2, a3,
                             __float_as_uint(pl0[nf]), __float_as_uint(pl1[nf]));
                }
            }
        }
    }
    #pragma unroll
    for (int half = 0; half < 2; half++)
        #pragma unroll
        for (int nf = 0; nf < 4; nf++) {
            int n = half * 32 + nf * 8 + 2 * tig;
            int r0 = row0 + rows0 + gid, r1 = r0 + 8;
            if (r0 < M) g_hW[(size_t)r0 * 32 + (n >> 1)] = pack_bf(c[half][nf][0], c[half][nf][1]);
            if (r1 < M) g_hW[(size_t)r1 * 32 + (n >> 1)] = pack_bf(c[half][nf][2], c[half][nf][3]);
        }
}

// ---------------------------------------------------------------------------
// Node MLP: affine+ReLU, GEMM1(+bias,ReLU), GEMM2 -> bf16 hW or pooling.
// 128 rows/block, warp-exclusive rows, fragment-major weight planes.
template <bool NEXT>
__global__ __launch_bounds__(256) void node_kernel(
    const float* __restrict__ ba, const float* __restrict__ gam,
    const float* __restrict__ bet, int wb_off,
    const float* __restrict__ bb, int wn_off,
    const void* __restrict__ batchp, int M)
{
    extern __shared__ float sm[];
    float* zs = sm;                 // 128 x 68 (z, later h)
    float* Wh = zs + 128 * 68;      // 4096 (fragment-major)
    float* Wl = Wh + 4096;          // 4096
    __shared__ float A[64], Bc[64], bbs[64];
    __shared__ int sbat[128];

    const int t = threadIdx.x;
    const int row0 = blockIdx.x * 128;

    if (t < 64) {
        float inv = rsqrtf(1.0f + 1e-5f);
        float a = gam[t] * inv;
        A[t] = a;
        Bc[t] = ba[t] * a + bet[t];
        bbs[t] = bb[t];
    }
    for (int i = t; i < 64 * 16; i += 256) {
        int k = i >> 4, q = i & 15;
        float4 h4 = *(const float4*)(g_whi + wb_off + k * 64 + q * 4);
        float4 l4 = *(const float4*)(g_wlo + wb_off + k * 64 + q * 4);
        stage_frag(Wh, k, q * 4, h4);
        stage_frag(Wl, k, q * 4, l4);
    }
    __syncthreads();   // A/Bc ready

    for (int i = t; i < 128 * 16; i += 256) {
        int r = i >> 4, q = i & 15;
        int gr = row0 + r; if (gr >= M) gr = M - 1;
        float4 v = *(const float4*)(g_acc + (size_t)gr * DIM + q * 4);
        int cc = q * 4;
        v.x = tf32r(fmaxf(v.x * A[cc + 0] + Bc[cc + 0], 0.0f));
        v.y = tf32r(fmaxf(v.y * A[cc + 1] + Bc[cc + 1], 0.0f));
        v.z = tf32r(fmaxf(v.z * A[cc + 2] + Bc[cc + 2], 0.0f));
        v.w = tf32r(fmaxf(v.w * A[cc + 3] + Bc[cc + 3], 0.0f));
        *(float4*)(zs + r * 68 + cc) = v;
    }
    __syncthreads();

    const int w = t >> 5, lane = t & 31;
    const int gid = lane >> 2, tig = lane & 3;
    const int rows0 = w * 16;

    // ---- GEMM1: h = relu(z @ Wb + bb) ----
    float c1[2][4][4] = {};
    #pragma unroll
    for (int k0 = 0; k0 < 8; k0++) {
        const int k = k0 * 8;
        int i0 = (rows0 + gid) * 68 + k + tig;
        int i1 = (rows0 + gid + 8) * 68 + k + tig;
        uint32_t a0 = __float_as_uint(zs[i0]);
        uint32_t a1 = __float_as_uint(zs[i1]);
        uint32_t a2 = __float_as_uint(zs[i0 + 4]);
        uint32_t a3 = __float_as_uint(zs[i1 + 4]);
        #pragma unroll
        for (int half = 0; half < 2; half++) {
            int bb2 = ((k + tig) * 2 + half) * 32 + gid * 4;
            float4 bh0 = *(float4*)(Wh + bb2);
            float4 bh1 = *(float4*)(Wh + bb2 + 256);
            float4 bl0 = *(float4*)(Wl + bb2);
            float4 bl1 = *(float4*)(Wl + bb2 + 256);
            const float* ph0 = (const float*)&bh0;
            const float* ph1 = (const float*)&bh1;
            const float* pl0 = (const float*)&bl0;
            const float* pl1 = (const float*)&bl1;
            #pragma unroll
            for (int nf = 0; nf < 4; nf++) {
                mma_tf32(c1[half][nf], a0, a1, a2, a3,
                         __float_as_uint(ph0[nf]), __float_as_uint(ph1[nf]));
                mma_tf32(c1[half][nf], a0, a1, a2, a3,
                         __float_as_uint(pl0[nf]), __float_as_uint(pl1[nf]));
            }
        }
    }
    // epilogue into OWN rows (warp-exclusive, no barrier needed)
    #pragma unroll
    for (int half = 0; half < 2; half++)
        #pragma unroll
        for (int nf = 0; nf < 4; nf++) {
            int n = half * 32 + nf * 8 + 2 * tig;
            int r0 = rows0 + gid, r1 = r0 + 8;
            float h00 = fmaxf(c1[half][nf][0] + bbs[n],     0.0f);
            float h01 = fmaxf(c1[half][nf][1] + bbs[n + 1], 0.0f);
            float h10 = fmaxf(c1[half][nf][2] + bbs[n],     0.0f);
            float h11 = fmaxf(c1[half][nf][3] + bbs[n + 1], 0.0f);
            if (NEXT) { h00 = tf32r(h00); h01 = tf32r(h01); h10 = tf32r(h10); h11 = tf32r(h11); }
            zs[r0 * 68 + n]     = h00; zs[r0 * 68 + n + 1] = h01;
            zs[r1 * 68 + n]     = h10; zs[r1 * 68 + n + 1] = h11;
        }
    __syncthreads();   // GEMM1 done; weight planes free; h visible

    if (NEXT) {
        for (int i = t; i < 64 * 16; i += 256) {
            int k = i >> 4, q = i & 15;
            float4 h4 = *(const float4*)(g_whi + wn_off + k * 64 + q * 4);
            float4 l4 = *(const float4*)(g_wlo + wn_off + k * 64 + q * 4);
            stage_frag(Wh, k, q * 4, h4);
            stage_frag(Wl, k, q * 4, l4);
        }
        __syncthreads();

        // ---- GEMM2: hW' = h @ Wn -> g_hW (bf16) ----
        float c2[2][4][4] = {};
        #pragma unroll
        for (int k0 = 0; k0 < 8; k0++) {
            const int k = k0 * 8;
            int i0 = (rows0 + gid) * 68 + k + tig;
            int i1 = (rows0 + gid + 8) * 68 + k + tig;
            uint32_t a0 = __float_as_uint(zs[i0]);
            uint32_t a1 = __float_as_uint(zs[i1]);
            uint32_t a2 = __float_as_uint(zs[i0 + 4]);
            uint32_t a3 = __float_as_uint(zs[i1 + 4]);
            #pragma unroll
            for (int half = 0; half < 2; half++) {
                int bb2 = ((k + tig) * 2 + half) * 32 + gid * 4;
                float4 bh0 = *(float4*)(Wh + bb2);
                float4 bh1 = *(float4*)(Wh + bb2 + 256);
                float4 bl0 = *(float4*)(Wl + bb2);
                float4 bl1 = *(float4*)(Wl + bb2 + 256);
                const float* ph0 = (const float*)&bh0;
                const float* ph1 = (const float*)&bh1;
                const float* pl0 = (const float*)&bl0;
                const float* pl1 = (const float*)&bl1;
                #pragma unroll
                for (int nf = 0; nf < 4; nf++) {
                    mma_tf32(c2[half][nf], a0, a1, a2, a3,
                             __float_as_uint(ph0[nf]), __float_as_uint(ph1[nf]));
                    mma_tf32(c2[half][nf], a0, a1, a2, a3,
                             __float_as_uint(pl0[nf]), __float_as_uint(pl1[nf]));
                }
            }
        }
        #pragma unroll
        for (int half = 0; half < 2; half++)
            #pragma unroll
            for (int nf = 0; nf < 4; nf++) {
                int n = half * 32 + nf * 8 + 2 * tig;
                int r0 = row0 + rows0 + gid, r1 = r0 + 8;
                if (r0 < M) g_hW[(size_t)r0 * 32 + (n >> 1)] = pack_bf(c2[half][nf][0], c2[half][nf][1]);
                if (r1 < M) g_hW[(size_t)r1 * 32 + (n >> 1)] = pack_bf(c2[half][nf][2], c2[half][nf][3]);
            }
    } else {
        // ---- pooling (batch sorted): run-length reduce per column ----
        for (int i = t; i < 128; i += 256) {
            int gr = row0 + i;
            int b = -1;
            if (gr < M) {
                if (g_is64) b = (int)((const long long*)batchp)[gr];
                else        b = ((const int*)batchp)[gr];
            }
            sbat[i] = b;
        }
        __syncthreads();
        if (t < 64) {
            const int c = t;
            float s = 0.0f;
            int cur = sbat[0];
            for (int r = 0; r < 128; r++) {
                int b = sbat[r];
                if (b < 0) break;
                if (b != cur) {
                    atomicAdd(&g_pool[cur * DIM + c], s);
                    s = 0.0f; cur = b;
                }
                s += zs[r * 68 + c];
            }
            if (cur >= 0) atomicAdd(&g_pool[cur * DIM + c], s);
        }
    }
}

// ---------------------------------------------------------------------------
__global__ __launch_bounds__(256) void cls_kernel(
    const float* __restrict__ Wl1, const float* __restrict__ bl1,
    const float* __restrict__ Wl2, const float* __restrict__ bl2,
    float* __restrict__ out)
{
    extern __shared__ float sm[];
    float* ps  = sm;             // 64 x 64 pooled
    float* Ws1 = ps + 4096;      // 64 x 64 summed Wl1
    float* z1  = Ws1 + 4096;     // 64 x 65
    const int t = threadIdx.x;

    for (int i = t; i < 4096; i += 256) {
        ps[i]  = g_pool[i];
        Ws1[i] = Wl1[i] + Wl1[4096 + i] + Wl1[8192 + i];
    }
    __syncthreads();

    const int c = t & 63;
    const int gbase = (t >> 6) * 16;
    for (int gg = 0; gg < 16; gg++) {
        int g = gbase + gg;
        float s = bl1[c];
        #pragma unroll 8
        for (int k = 0; k < 64; k++) s += ps[g * 64 + k] * Ws1[k * 64 + c];
        z1[g * 65 + c] = fmaxf(s, 0.0f);
    }
    __syncthreads();

    if (t < 64) {
        const int g = t;
        float a = bl2[0], b = bl2[1];
        #pragma unroll 8
        for (int k = 0; k < 64; k++) {
            float v = z1[g * 65 + k];
            a += v * Wl2[k * 2 + 0];
            b += v * Wl2[k * 2 + 1];
        }
        float m = fmaxf(a, b);
        float l = m + logf(expf(a - m) + expf(b - m));
        out[2 * g + 0] = a - l;
        out[2 * g + 1] = b - l;
    }
}

// ---------------------------------------------------------------------------
extern "C" void kernel_launch(void* const* d_in, const int* in_sizes, int n_in,
                              void* d_out, int out_size)
{
    const float* x     = (const float*)d_in[0];
    const void*  eidx  = d_in[1];
    const void*  batch = d_in[2];
    const float* W0a   = (const float*)d_in[3];
    const float* b0a   = (const float*)d_in[4];
    const float* g0    = (const float*)d_in[5];
    const float* be0   = (const float*)d_in[6];
    const float* W0b   = (const float*)d_in[7];
    const float* b0b   = (const float*)d_in[8];
    const float* Wsa   = (const float*)d_in[9];
    const float* bsa   = (const float*)d_in[10];
    const float* gs    = (const float*)d_in[11];
    const float* bes   = (const float*)d_in[12];
    const float* Wsb   = (const float*)d_in[13];
    const float* bsb   = (const float*)d_in[14];
    const float* Wl1   = (const float*)d_in[15];
    const float* bl1   = (const float*)d_in[16];
    const float* Wl2   = (const float*)d_in[17];
    const float* bl2   = (const float*)d_in[18];

    const int M = in_sizes[0] / 128;
    const int E = in_sizes[1] / 2;
    const int nblk = (M + 127) / 128;
    const int eblk = (E + 255) / 256;
    const int sblk = (M + 1023) / 1024;
    const int gblk = (M * 32 + 255) / 256;

    const size_t smem_lin0 = (128 * 132 + 4096 * 2) * sizeof(float);  // 100352
    const size_t smem_node = (128 * 68 + 4096 * 2) * sizeof(float);   // 67584
    const size_t smem_cls  = (4096 + 4096 + 64 * 65) * sizeof(float);

    cudaFuncSetAttribute(lin0_kernel, cudaFuncAttributeMaxDynamicSharedMemorySize, (int)smem_lin0);
    cudaFuncSetAttribute(node_kernel<true>, cudaFuncAttributeMaxDynamicSharedMemorySize, (int)smem_node);
    cudaFuncSetAttribute(node_kernel<false>, cudaFuncAttributeMaxDynamicSharedMemorySize, (int)smem_node);
    cudaFuncSetAttribute(cls_kernel, cudaFuncAttributeMaxDynamicSharedMemorySize, (int)smem_cls);

    // setup (zero + dtype detect + weight split)
    zero_split_kernel<<<64, 256>>>((const int*)eidx, M, W0a, W0b, Wsa, Wsb);

    // build dst-CSR once; reused by all 3 gathers
    hist_kernel<<<eblk, 256>>>(eidx, E);
    scan_local_kernel<<<sblk, 256>>>(M);
    scan_add_kernel<<<(M + 256) / 256 + 1, 256>>>(M, E);
    reorder_kernel<<<eblk, 256>>>(eidx, E);

    lin0_kernel<<<nblk, 256, smem_lin0>>>(x, M);
    gather_kernel<<<gblk, 256>>>(M);
    node_kernel<true><<<nblk, 256, smem_node>>>(b0a, g0, be0, OFF_W0B, b0b, OFF_WSA0, nullptr, M);
    gather_kernel<<<gblk, 256>>>(M);
    node_kernel<true><<<nblk, 256, smem_node>>>(bsa, gs, bes, OFF_WSB0, bsb, OFF_WSA1, nullptr, M);
    gather_kernel<<<gblk, 256>>>(M);
    node_kernel<false><<<nblk, 256, smem_node>>>(bsa + 64, gs + 64, bes + 64, OFF_WSB1,
                                                 bsb + 64, 0, batch, M);
    cls_kernel<<<1, 256, smem_cls>>>(Wl1, bl1, Wl2, bl2, (float*)d_out);
}

// round 14
// speedup vs baseline: 1.7433x; 1.7433x over previous
#include <cuda_runtime.h>
#include <cuda_bf16.h>
#include <math.h>
#include <stdint.h>

#define NMAX 100000
#define EMAX 1600000
#define DIM 64

// node features stored as bf16 (32 uints = 64 bf16 per row)
__device__ unsigned int g_hW[(size_t)NMAX * 32];
__device__ float g_acc[(size_t)NMAX * DIM];
__device__ float g_pool[64 * DIM];
__device__ int   g_is64;
__device__ int   g_deg[NMAX];
__device__ int   g_off[NMAX + 1];
__device__ int   g_cursor[NMAX];
__device__ int   g_bsum[1024];
__device__ int   g_srcs[EMAX];

// packed bf16 weight planes (hi/lo), pair-of-k per uint:
// Wp[kp][n] = pack(W[2kp][n], W[2kp+1][n]); matrices: W0a|W0b|Wsb0|Wsb1|Wsa0|Wsa1
#define PW_W0A  0
#define PW_W0B  4096
#define PW_WSB0 6144
#define PW_WSB1 8192
#define PW_WSA0 10240
#define PW_WSA1 12288
#define PW_TOTAL 14336
__device__ unsigned int g_wph[PW_TOTAL];
__device__ unsigned int g_wpl[PW_TOTAL];

// ---------------------------------------------------------------------------
__device__ __forceinline__ void mma_bf16(float* c, uint32_t a0, uint32_t a1,
                                         uint32_t a2, uint32_t a3,
                                         uint32_t b0, uint32_t b1) {
    asm volatile(
        "mma.sync.aligned.m16n8k16.row.col.f32.bf16.bf16.f32 "
        "{%0,%1,%2,%3}, {%4,%5,%6,%7}, {%8,%9}, {%0,%1,%2,%3};"
        : "+f"(c[0]), "+f"(c[1]), "+f"(c[2]), "+f"(c[3])
        : "r"(a0), "r"(a1), "r"(a2), "r"(a3), "r"(b0), "r"(b1));
}

__device__ __forceinline__ unsigned int pack_bf(float a, float b) {
    __nv_bfloat162 p = __floats2bfloat162_rn(a, b);
    return *(unsigned int*)&p;
}

__device__ __forceinline__ float4 unpack_bf4(uint2 u) {
    float2 f0 = __bfloat1622float2(*(__nv_bfloat162*)&u.x);
    float2 f1 = __bfloat1622float2(*(__nv_bfloat162*)&u.y);
    return make_float4(f0.x, f0.y, f1.x, f1.y);
}

// ---------------------------------------------------------------------------
// zero + dtype detect + bf16 hi/lo weight packing (fused setup kernel)
__global__ void zero_split_kernel(const int* __restrict__ e, int M,
    const float* __restrict__ W0a, const float* __restrict__ W0b,
    const float* __restrict__ Wsa, const float* __restrict__ Wsb)
{
    int t = blockIdx.x * blockDim.x + threadIdx.x;   // 64*256 = 16384 threads
    if (t == 0) {
        int all0 = 1;
        #pragma unroll
        for (int i = 1; i < 64; i += 2) all0 &= (e[i] == 0);
        g_is64 = all0;
    }
    if (t < 64 * DIM) g_pool[t] = 0.0f;
    for (int i = t; i < M; i += 16384) g_deg[i] = 0;
    for (int j = t; j < PW_TOTAL; j += 16384) {
        const float* src; int loc;
        if      (j < PW_W0B)  { src = W0a;        loc = j; }
        else if (j < PW_WSB0) { src = W0b;        loc = j - PW_W0B; }
        else if (j < PW_WSB1) { src = Wsb;        loc = j - PW_WSB0; }
        else if (j < PW_WSA0) { src = Wsb + 4096; loc = j - PW_WSB1; }
        else if (j < PW_WSA1) { src = Wsa;        loc = j - PW_WSA0; }
        else                  { src = Wsa + 4096; loc = j - PW_WSA1; }
        int kp = loc >> 6, n = loc & 63;
        float w0 = src[kp * 128 + n];
        float w1 = src[kp * 128 + 64 + n];
        __nv_bfloat16 h0 = __float2bfloat16_rn(w0);
        __nv_bfloat16 h1 = __float2bfloat16_rn(w1);
        float l0f = w0 - __bfloat162float(h0);
        float l1f = w1 - __bfloat162float(h1);
        g_wph[j] = pack_bf(__bfloat162float(h0), __bfloat162float(h1));
        g_wpl[j] = pack_bf(l0f, l1f);
    }
}

// ---------------------------------------------------------------------------
// CSR build
__global__ __launch_bounds__(256) void hist_kernel(const void* __restrict__ eidx, int E) {
    int e = blockIdx.x * 256 + threadIdx.x;
    if (e >= E) return;
    int dst;
    if (g_is64) dst = (int)__ldg(&((const long long*)eidx)[E + e]);
    else        dst = __ldg(&((const int*)eidx)[E + e]);
    atomicAdd(&g_deg[dst], 1);
}

__global__ __launch_bounds__(256) void scan_local_kernel(int M) {
    __shared__ int warp_tot[8];
    __shared__ int wbase[8];
    const int t = threadIdx.x;
    const int idx0 = blockIdx.x * 1024 + t * 4;
    int v[4];
    #pragma unroll
    for (int i = 0; i < 4; i++) v[i] = (idx0 + i < M) ? g_deg[idx0 + i] : 0;
    int tot = v[0] + v[1] + v[2] + v[3];
    const int lane = t & 31, w = t >> 5;
    int sc = tot;
    #pragma unroll
    for (int o = 1; o < 32; o <<= 1) {
        int n = __shfl_up_sync(0xffffffffu, sc, o);
        if (lane >= o) sc += n;
    }
    if (lane == 31) warp_tot[w] = sc;
    __syncthreads();
    if (t == 0) {
        int s = 0;
        #pragma unroll
        for (int i = 0; i < 8; i++) { wbase[i] = s; s += warp_tot[i]; }
        g_bsum[blockIdx.x] = s;
    }
    __syncthreads();
    int run = sc - tot + wbase[w];
    #pragma unroll
    for (int i = 0; i < 4; i++) {
        if (idx0 + i < M) g_off[idx0 + i] = run;
        run += v[i];
    }
}

__global__ __launch_bounds__(256) void scan_add_kernel(int M, int E) {
    __shared__ int red[256];
    const int t = threadIdx.x;
    const int nb = blockIdx.x >> 2;        // 256-chunks never cross 1024-chunks
    int s = 0;
    for (int i = t; i < nb; i += 256) s += g_bsum[i];
    red[t] = s;
    __syncthreads();
    #pragma unroll
    for (int o = 128; o > 0; o >>= 1) {
        if (t < o) red[t] += red[t + o];
        __syncthreads();
    }
    const int base = red[0];
    int i = blockIdx.x * 256 + t;
    if (i < M) {
        int o = g_off[i] + base;
        g_off[i] = o;
        g_cursor[i] = o;
    } else if (i == M) {
        g_off[M] = E;
    }
}

__global__ __launch_bounds__(256) void reorder_kernel(const void* __restrict__ eidx, int E) {
    int e = blockIdx.x * 256 + threadIdx.x;
    if (e >= E) return;
    int src, dst;
    if (g_is64) {
        const long long* p = (const long long*)eidx;
        src = (int)__ldg(&p[e]); dst = (int)__ldg(&p[E + e]);
    } else {
        const int* p = (const int*)eidx;
        src = __ldg(&p[e]); dst = __ldg(&p[E + e]);
    }
    int pos = atomicAdd(&g_cursor[dst], 1);
    g_srcs[pos] = src;
}

// ---------------------------------------------------------------------------
// Gather: one warp per dst node; half-warp h, lane j owns uint2 j (4 bf16).
__global__ __launch_bounds__(256) void gather_kernel(int M) {
    const int warp = (blockIdx.x * 256 + threadIdx.x) >> 5;
    if (warp >= M) return;
    const int lane = threadIdx.x & 31;
    const int h = lane >> 4;
    const int j = lane & 15;

    const uint2* hw = (const uint2*)g_hW;
    const int beg = g_off[warp], end = g_off[warp + 1];
    float4 acc = make_float4(0.f, 0.f, 0.f, 0.f);
    int k = beg + h;
    for (; k + 6 < end; k += 8) {
        int s0 = __ldg(&g_srcs[k]);
        int s1 = __ldg(&g_srcs[k + 2]);
        int s2 = __ldg(&g_srcs[k + 4]);
        int s3 = __ldg(&g_srcs[k + 6]);
        float4 v0 = unpack_bf4(__ldg(hw + (size_t)s0 * 16 + j));
        float4 v1 = unpack_bf4(__ldg(hw + (size_t)s1 * 16 + j));
        float4 v2 = unpack_bf4(__ldg(hw + (size_t)s2 * 16 + j));
        float4 v3 = unpack_bf4(__ldg(hw + (size_t)s3 * 16 + j));
        acc.x += (v0.x + v1.x) + (v2.x + v3.x);
        acc.y += (v0.y + v1.y) + (v2.y + v3.y);
        acc.z += (v0.z + v1.z) + (v2.z + v3.z);
        acc.w += (v0.w + v1.w) + (v2.w + v3.w);
    }
    for (; k < end; k += 2) {
        int s0 = __ldg(&g_srcs[k]);
        float4 v0 = unpack_bf4(__ldg(hw + (size_t)s0 * 16 + j));
        acc.x += v0.x; acc.y += v0.y; acc.z += v0.z; acc.w += v0.w;
    }
    acc.x += __shfl_down_sync(0xffffffffu, acc.x, 16);
    acc.y += __shfl_down_sync(0xffffffffu, acc.y, 16);
    acc.z += __shfl_down_sync(0xffffffffu, acc.z, 16);
    acc.w += __shfl_down_sync(0xffffffffu, acc.w, 16);
    if (h == 0) {
        float4 self = unpack_bf4(__ldg(hw + (size_t)warp * 16 + j));
        acc.x += self.x; acc.y += self.y; acc.z += self.z; acc.w += self.w;
        *((float4*)(g_acc + (size_t)warp * DIM) + j) = acc;
    }
}

// ---------------------------------------------------------------------------
// Layer-0 first linear: hW = X[M,128] @ W0a[128,64] -> bf16.
// bf16 m16n8k16 MMA, weights = hi+lo packed planes. 128 rows/block.
// Strides (uints): Xs=68, Wp=72 -> conflict-free fragment loads.
__global__ __launch_bounds__(256) void lin0_kernel(const float* __restrict__ X, int M)
{
    extern __shared__ unsigned int smu[];
    unsigned int* Xs = smu;             // 128 x 68
    unsigned int* Wh = Xs + 128 * 68;   // 64 x 72 (kp rows)
    unsigned int* Wl = Wh + 64 * 72;    // 64 x 72
    const int t = threadIdx.x;
    const int row0 = blockIdx.x * 128;

    // stage X packed bf16x2
    for (int i = t; i < 128 * 32; i += 256) {
        int r = i >> 5, kk = i & 31;
        int gr = row0 + r; if (gr >= M) gr = M - 1;
        float4 v = *(const float4*)(X + (size_t)gr * 128 + kk * 4);
        Xs[r * 68 + kk * 2]     = pack_bf(v.x, v.y);
        Xs[r * 68 + kk * 2 + 1] = pack_bf(v.z, v.w);
    }
    // stage weight planes (uint4 copies)
    for (int i = t; i < 64 * 16; i += 256) {
        int k = i >> 4, q = i & 15;
        *(uint4*)(Wh + k * 72 + q * 4) = *(const uint4*)(g_wph + PW_W0A + k * 64 + q * 4);
        *(uint4*)(Wl + k * 72 + q * 4) = *(const uint4*)(g_wpl + PW_W0A + k * 64 + q * 4);
    }
    __syncthreads();

    const int w = t >> 5, lane = t & 31;
    const int gid = lane >> 2, tig = lane & 3;
    const int rows0 = w * 16;           // warp-exclusive rows

    float c[2][4][4] = {};
    #pragma unroll
    for (int kt = 0; kt < 8; kt++) {    // K=128 -> 8 k16 tiles
        int i0 = (rows0 + gid) * 68 + kt * 8 + tig;
        int i1 = (rows0 + gid + 8) * 68 + kt * 8 + tig;
        uint32_t a0 = Xs[i0];
        uint32_t a1 = Xs[i1];
        uint32_t a2 = Xs[i0 + 4];
        uint32_t a3 = Xs[i1 + 4];
        #pragma unroll
        for (int half = 0; half < 2; half++) {
            #pragma unroll
            for (int nf = 0; nf < 4; nf++) {
                int n = half * 32 + nf * 8 + gid;
                int b0i = (kt * 8 + tig) * 72 + n, b1i = b0i + 288; // +4 rows
                mma_bf16(c[half][nf], a0, a1, a2, a3, Wh[b0i], Wh[b1i]);
                mma_bf16(c[half][nf], a0, a1, a2, a3, Wl[b0i], Wl[b1i]);
            }
        }
    }
    #pragma unroll
    for (int half = 0; half < 2; half++)
        #pragma unroll
        for (int nf = 0; nf < 4; nf++) {
            int n = half * 32 + nf * 8 + 2 * tig;
            int r0 = row0 + rows0 + gid, r1 = r0 + 8;
            if (r0 < M) g_hW[(size_t)r0 * 32 + (n >> 1)] = pack_bf(c[half][nf][0], c[half][nf][1]);
            if (r1 < M) g_hW[(size_t)r1 * 32 + (n >> 1)] = pack_bf(c[half][nf][2], c[half][nf][3]);
        }
}

// ---------------------------------------------------------------------------
// Node MLP: affine+ReLU -> bf16 z, GEMM1(+bias,ReLU) -> bf16 h,
// GEMM2 -> bf16 hW or pooling. 128 rows/block, warp-exclusive rows.
// Strides (uints): zs=36, Wp=72.
template <bool NEXT>
__global__ __launch_bounds__(256) void node_kernel(
    const float* __restrict__ ba, const float* __restrict__ gam,
    const float* __restrict__ bet, int wb_off,
    const float* __restrict__ bb, int wn_off,
    const void* __restrict__ batchp, int M)
{
    extern __shared__ unsigned int smu[];
    unsigned int* zs = smu;             // 128 x 36 (z, later h) packed bf16x2
    unsigned int* Wh = zs + 128 * 36;   // 32 x 72
    unsigned int* Wl = Wh + 32 * 72;    // 32 x 72
    __shared__ float A[64], Bc[64], bbs[64];
    __shared__ int sbat[128];

    const int t = threadIdx.x;
    const int row0 = blockIdx.x * 128;

    if (t < 64) {
        float inv = rsqrtf(1.0f + 1e-5f);
        float a = gam[t] * inv;
        A[t] = a;
        Bc[t] = ba[t] * a + bet[t];
        bbs[t] = bb[t];
    }
    // stage Wb planes (uint4 copies)
    for (int i = t; i < 32 * 16; i += 256) {
        int k = i >> 4, q = i & 15;
        *(uint4*)(Wh + k * 72 + q * 4) = *(const uint4*)(g_wph + wb_off + k * 64 + q * 4);
        *(uint4*)(Wl + k * 72 + q * 4) = *(const uint4*)(g_wpl + wb_off + k * 64 + q * 4);
    }
    __syncthreads();   // A/Bc ready

    // stage z = bf16(relu(affine(acc)))
    for (int i = t; i < 128 * 16; i += 256) {
        int r = i >> 4, q = i & 15;
        int gr = row0 + r; if (gr >= M) gr = M - 1;
        float4 v = *(const float4*)(g_acc + (size_t)gr * DIM + q * 4);
        int cc = q * 4;
        v.x = fmaxf(v.x * A[cc + 0] + Bc[cc + 0], 0.0f);
        v.y = fmaxf(v.y * A[cc + 1] + Bc[cc + 1], 0.0f);
        v.z = fmaxf(v.z * A[cc + 2] + Bc[cc + 2], 0.0f);
        v.w = fmaxf(v.w * A[cc + 3] + Bc[cc + 3], 0.0f);
        zs[r * 36 + q * 2]     = pack_bf(v.x, v.y);
        zs[r * 36 + q * 2 + 1] = pack_bf(v.z, v.w);
    }
    __syncthreads();

    const int w = t >> 5, lane = t & 31;
    const int gid = lane >> 2, tig = lane & 3;
    const int rows0 = w * 16;

    // ---- GEMM1: h = relu(z @ Wb + bb) ----
    float c1[2][4][4] = {};
    #pragma unroll
    for (int kt = 0; kt < 4; kt++) {    // K=64 -> 4 k16 tiles
        int i0 = (rows0 + gid) * 36 + kt * 8 + tig;
        int i1 = (rows0 + gid + 8) * 36 + kt * 8 + tig;
        uint32_t a0 = zs[i0];
        uint32_t a1 = zs[i1];
        uint32_t a2 = zs[i0 + 4];
        uint32_t a3 = zs[i1 + 4];
        #pragma unroll
        for (int half = 0; half < 2; half++) {
            #pragma unroll
            for (int nf = 0; nf < 4; nf++) {
                int n = half * 32 + nf * 8 + gid;
                int b0i = (kt * 8 + tig) * 72 + n, b1i = b0i + 288;
                mma_bf16(c1[half][nf], a0, a1, a2, a3, Wh[b0i], Wh[b1i]);
                mma_bf16(c1[half][nf], a0, a1, a2, a3, Wl[b0i], Wl[b1i]);
            }
        }
    }
    // epilogue into OWN rows (warp-exclusive): pack bf16 pairs
    #pragma unroll
    for (int half = 0; half < 2; half++)
        #pragma unroll
        for (int nf = 0; nf < 4; nf++) {
            int n = half * 32 + nf * 8 + 2 * tig;
            int r0 = rows0 + gid, r1 = r0 + 8;
            float h00 = fmaxf(c1[half][nf][0] + bbs[n],     0.0f);
            float h01 = fmaxf(c1[half][nf][1] + bbs[n + 1], 0.0f);
            float h10 = fmaxf(c1[half][nf][2] + bbs[n],     0.0f);
            float h11 = fmaxf(c1[half][nf][3] + bbs[n + 1], 0.0f);
            zs[r0 * 36 + (n >> 1)] = pack_bf(h00, h01);
            zs[r1 * 36 + (n >> 1)] = pack_bf(h10, h11);
        }
    __syncthreads();   // GEMM1 done; weight planes free; h visible

    if (NEXT) {
        for (int i = t; i < 32 * 16; i += 256) {
            int k = i >> 4, q = i & 15;
            *(uint4*)(Wh + k * 72 + q * 4) = *(const uint4*)(g_wph + wn_off + k * 64 + q * 4);
            *(uint4*)(Wl + k * 72 + q * 4) = *(const uint4*)(g_wpl + wn_off + k * 64 + q * 4);
        }
        __syncthreads();

        // ---- GEMM2: hW' = h @ Wn -> g_hW (bf16) ----
        float c2[2][4][4] = {};
        #pragma unroll
        for (int kt = 0; kt < 4; kt++) {
            int i0 = (rows0 + gid) * 36 + kt * 8 + tig;
            int i1 = (rows0 + gid + 8) * 36 + kt * 8 + tig;
            uint32_t a0 = zs[i0];
            uint32_t a1 = zs[i1];
            uint32_t a2 = zs[i0 + 4];
            uint32_t a3 = zs[i1 + 4];
            #pragma unroll
            for (int half = 0; half < 2; half++) {
                #pragma unroll
                for (int nf = 0; nf < 4; nf++) {
                    int n = half * 32 + nf * 8 + gid;
                    int b0i = (kt * 8 + tig) * 72 + n, b1i = b0i + 288;
                    mma_bf16(c2[half][nf], a0, a1, a2, a3, Wh[b0i], Wh[b1i]);
                    mma_bf16(c2[half][nf], a0, a1, a2, a3, Wl[b0i], Wl[b1i]);
                }
            }
        }
        #pragma unroll
        for (int half = 0; half < 2; half++)
            #pragma unroll
            for (int nf = 0; nf < 4; nf++) {
                int n = half * 32 + nf * 8 + 2 * tig;
                int r0 = row0 + rows0 + gid, r1 = r0 + 8;
                if (r0 < M) g_hW[(size_t)r0 * 32 + (n >> 1)] = pack_bf(c2[half][nf][0], c2[half][nf][1]);
                if (r1 < M) g_hW[(size_t)r1 * 32 + (n >> 1)] = pack_bf(c2[half][nf][2], c2[half][nf][3]);
            }
    } else {
        // ---- pooling (batch sorted): run-length reduce per column ----
        for (int i = t; i < 128; i += 256) {
            int gr = row0 + i;
            int b = -1;
            if (gr < M) {
                if (g_is64) b = (int)((const long long*)batchp)[gr];
                else        b = ((const int*)batchp)[gr];
            }
            sbat[i] = b;
        }
        __syncthreads();
        if (t < 64) {
            const int c = t;
            float s = 0.0f;
            int cur = sbat[0];
            for (int r = 0; r < 128; r++) {
                int b = sbat[r];
                if (b < 0) break;
                if (b != cur) {
                    atomicAdd(&g_pool[cur * DIM + c], s);
                    s = 0.0f; cur = b;
                }
                unsigned int u = zs[r * 36 + (c >> 1)];
                __nv_bfloat162 p = *(__nv_bfloat162*)&u;
                s += (c & 1) ? __high2float(p) : __low2float(p);
            }
            if (cur >= 0) atomicAdd(&g_pool[cur * DIM + c], s);
        }
    }
}

// ---------------------------------------------------------------------------
__global__ __launch_bounds__(256) void cls_kernel(
    const float* __restrict__ Wl1, const float* __restrict__ bl1,
    const float* __restrict__ Wl2, const float* __restrict__ bl2,
    float* __restrict__ out)
{
    extern __shared__ float sm[];
    float* ps  = sm;             // 64 x 64 pooled
    float* Ws1 = ps + 4096;      // 64 x 64 summed Wl1
    float* z1  = Ws1 + 4096;     // 64 x 65
    const int t = threadIdx.x;

    for (int i = t; i < 4096; i += 256) {
        ps[i]  = g_pool[i];
        Ws1[i] = Wl1[i] + Wl1[4096 + i] + Wl1[8192 + i];
    }
    __syncthreads();

    const int c = t & 63;
    const int gbase = (t >> 6) * 16;
    for (int gg = 0; gg < 16; gg++) {
        int g = gbase + gg;
        float s = bl1[c];
        #pragma unroll 8
        for (int k = 0; k < 64; k++) s += ps[g * 64 + k] * Ws1[k * 64 + c];
        z1[g * 65 + c] = fmaxf(s, 0.0f);
    }
    __syncthreads();

    if (t < 64) {
        const int g = t;
        float a = bl2[0], b = bl2[1];
        #pragma unroll 8
        for (int k = 0; k < 64; k++) {
            float v = z1[g * 65 + k];
            a += v * Wl2[k * 2 + 0];
            b += v * Wl2[k * 2 + 1];
        }
        float m = fmaxf(a, b);
        float l = m + logf(expf(a - m) + expf(b - m));
        out[2 * g + 0] = a - l;
        out[2 * g + 1] = b - l;
    }
}

// ---------------------------------------------------------------------------
extern "C" void kernel_launch(void* const* d_in, const int* in_sizes, int n_in,
                              void* d_out, int out_size)
{
    const float* x     = (const float*)d_in[0];
    const void*  eidx  = d_in[1];
    const void*  batch = d_in[2];
    const float* W0a   = (const float*)d_in[3];
    const float* b0a   = (const float*)d_in[4];
    const float* g0    = (const float*)d_in[5];
    const float* be0   = (const float*)d_in[6];
    const float* W0b   = (const float*)d_in[7];
    const float* b0b   = (const float*)d_in[8];
    const float* Wsa   = (const float*)d_in[9];
    const float* bsa   = (const float*)d_in[10];
    const float* gs    = (const float*)d_in[11];
    const float* bes   = (const float*)d_in[12];
    const float* Wsb   = (const float*)d_in[13];
    const float* bsb   = (const float*)d_in[14];
    const float* Wl1   = (const float*)d_in[15];
    const float* bl1   = (const float*)d_in[16];
    const float* Wl2   = (const float*)d_in[17];
    const float* bl2   = (const float*)d_in[18];

    const int M = in_sizes[0] / 128;
    const int E = in_sizes[1] / 2;
    const int nblk = (M + 127) / 128;
    const int eblk = (E + 255) / 256;
    const int sblk = (M + 1023) / 1024;
    const int gblk = (M * 32 + 255) / 256;

    const size_t smem_lin0 = (128 * 68 + 64 * 72 * 2) * sizeof(int);   // 71680
    const size_t smem_node = (128 * 36 + 32 * 72 * 2) * sizeof(int);   // 36864
    const size_t smem_cls  = (4096 + 4096 + 64 * 65) * sizeof(float);

    cudaFuncSetAttribute(lin0_kernel, cudaFuncAttributeMaxDynamicSharedMemorySize, (int)smem_lin0);
    cudaFuncSetAttribute(node_kernel<true>, cudaFuncAttributeMaxDynamicSharedMemorySize, (int)smem_node);
    cudaFuncSetAttribute(node_kernel<false>, cudaFuncAttributeMaxDynamicSharedMemorySize, (int)smem_node);
    cudaFuncSetAttribute(cls_kernel, cudaFuncAttributeMaxDynamicSharedMemorySize, (int)smem_cls);

    // setup (zero + dtype detect + bf16 weight packing)
    zero_split_kernel<<<64, 256>>>((const int*)eidx, M, W0a, W0b, Wsa, Wsb);

    // build dst-CSR once; reused by all 3 gathers
    hist_kernel<<<eblk, 256>>>(eidx, E);
    scan_local_kernel<<<sblk, 256>>>(M);
    scan_add_kernel<<<(M + 256) / 256 + 1, 256>>>(M, E);
    reorder_kernel<<<eblk, 256>>>(eidx, E);

    lin0_kernel<<<nblk, 256, smem_lin0>>>(x, M);
    gather_kernel<<<gblk, 256>>>(M);
    node_kernel<true><<<nblk, 256, smem_node>>>(b0a, g0, be0, PW_W0B, b0b, PW_WSA0, nullptr, M);
    gather_kernel<<<gblk, 256>>>(M);
    node_kernel<true><<<nblk, 256, smem_node>>>(bsa, gs, bes, PW_WSB0, bsb, PW_WSA1, nullptr, M);
    gather_kernel<<<gblk, 256>>>(M);
    node_kernel<false><<<nblk, 256, smem_node>>>(bsa + 64, gs + 64, bes + 64, PW_WSB1,
                                                 bsb + 64, 0, batch, M);
    cls_kernel<<<1, 256, smem_cls>>>(Wl1, bl1, Wl2, bl2, (float*)d_out);
}